// round 5
// baseline (speedup 1.0000x reference)
#include <cuda_runtime.h>

#define HW      256
#define NB      8
#define CH      64
#define HWHW    65536
#define NUNITS  (NB * HW)     // 2048 row-units (b*256 + row)
#define GRID    296           // persistent blocks, all resident (2/SM)
#define THREADS 512
#define ITERS   7             // ceil(2048/296)

__device__ float g_n1[NUNITS * HW];
__device__ float g_n2[NUNITS * HW];
__device__ int   g_flag[NUNITS];

__global__ void k_reset() {
    g_flag[blockIdx.x * blockDim.x + threadIdx.x] = 0;
}

__global__ void __launch_bounds__(THREADS, 2)
k_fused(const float* __restrict__ x1, const float* __restrict__ x2,
        const float* __restrict__ w,  const float* __restrict__ bias,
        float* __restrict__ out) {
    __shared__ float4 part1[4][64], part2[4][64];   // producer reduction, 8 KB
    __shared__ volatile int cons_prog;              // completed consumer iterations

    const int tid = threadIdx.x;
    const int bid = blockIdx.x;

    if (tid == 0) cons_prog = 0;
    __syncthreads();    // the ONLY full-block barrier

    if (tid < 256) {
        // ================= PRODUCER group (warps 0-7) =================
        const int q  = tid & 63;    // pixel quad (cols 4q..4q+3)
        const int cs = tid >> 6;    // channel quarter (16 ch)

        for (int it = 0; it < ITERS; ++it) {
            // loose throttle: stay <=2 iterations ahead of consumer (L2 window)
            if (it >= 2) while (cons_prog < it - 1) {}

            const int up = bid + it * GRID;
            if (up < NUNITS) {
                const int b = up >> 8, row = up & 255;
                const size_t base = (size_t)(b * CH + cs * 16) * (HWHW / 4)
                                  + (size_t)row * (HW / 4) + q;
                const float4* p1 = (const float4*)x1 + base;
                const float4* p2 = (const float4*)x2 + base;

                float4 s1 = make_float4(0.f, 0.f, 0.f, 0.f);
                float4 s2 = make_float4(0.f, 0.f, 0.f, 0.f);
#pragma unroll
                for (int c = 0; c < 16; ++c) {
                    const float4 a = p1[(size_t)c * (HWHW / 4)];
                    const float4 v = p2[(size_t)c * (HWHW / 4)];
                    s1.x += fabsf(a.x); s1.y += fabsf(a.y);
                    s1.z += fabsf(a.z); s1.w += fabsf(a.w);
                    s2.x += fabsf(v.x); s2.y += fabsf(v.y);
                    s2.z += fabsf(v.z); s2.w += fabsf(v.w);
                }
                part1[cs][q] = s1;
                part2[cs][q] = s2;
                asm volatile("bar.sync 1, 256;" ::: "memory");

                if (tid < 128) {
                    const int qq = tid & 63;
                    const float4* src = (tid < 64) ? &part1[0][0] : &part2[0][0];
                    float*       dst = (tid < 64) ? g_n1 : g_n2;
                    const float4 a = src[0 * 64 + qq];
                    const float4 bb = src[1 * 64 + qq];
                    const float4 c = src[2 * 64 + qq];
                    const float4 d = src[3 * 64 + qq];
                    float4 r;
                    r.x = (a.x + bb.x) + (c.x + d.x);
                    r.y = (a.y + bb.y) + (c.y + d.y);
                    r.z = (a.z + bb.z) + (c.z + d.z);
                    r.w = (a.w + bb.w) + (c.w + d.w);
                    ((float4*)(dst + (size_t)up * HW))[qq] = r;
                    __threadfence();   // publish before flag
                }
                asm volatile("bar.sync 1, 256;" ::: "memory");
                if (tid == 0) atomicExch(&g_flag[up], 1);
            }
        }
    } else {
        // ================= CONSUMER group (warps 8-15) =================
        const int t  = tid - 256;
        const int g  = t & 63;      // float4 group (pixels 4g..4g+3)
        const int cs = t >> 6;      // channel quarter (16 ch)

        float wv[9];
#pragma unroll
        for (int i = 0; i < 9; i++) wv[i] = w[i];
        const float bv = bias[0];

        for (int j = 0; j < ITERS; ++j) {
            const int uc = bid + j * GRID;
            if (uc < NUNITS) {
                const int b = uc >> 8, row = uc & 255;

                if (t == 0) {
                    while (*(volatile int*)&g_flag[uc] == 0) {}
                    if (row > 0)   while (*(volatile int*)&g_flag[uc - 1] == 0) {}
                    if (row < 255) while (*(volatile int*)&g_flag[uc + 1] == 0) {}
                    __threadfence();   // acquire
                }
                asm volatile("bar.sync 2, 256;" ::: "memory");

                // blend factors for this thread's 4 pixels (L1/L2-hit loads)
                float4 F1, F2;
                float* pf1 = (float*)&F1;
                float* pf2 = (float*)&F2;
#pragma unroll
                for (int k = 0; k < 4; ++k) {
                    const int col = g * 4 + k;
                    float c1 = bv, c2 = bv;
#pragma unroll
                    for (int di = 0; di < 3; ++di) {
                        const int rr = row + di - 1;
                        if (rr < 0 || rr >= HW) continue;
                        const float* n1r = g_n1 + (size_t)(b * HW + rr) * HW;
                        const float* n2r = g_n2 + (size_t)(b * HW + rr) * HW;
#pragma unroll
                        for (int dj = 0; dj < 3; ++dj) {
                            const int cc = col + dj - 1;
                            if (cc < 0 || cc >= HW) continue;
                            const float ww = wv[di * 3 + dj];
                            c1 += ww * n1r[cc];
                            c2 += ww * n2r[cc];
                        }
                    }
                    const float rd = 1.0f / (c1 + c2);
                    pf1[k] = c1 * rd;
                    pf2[k] = c2 * rd;
                }

                // stream 16 channels (L2-hit reads, streaming writes)
                const size_t fbase = (size_t)(b * CH + cs * 16) * (HWHW / 4)
                                   + (size_t)row * (HW / 4) + g;
                const float4* p1 = (const float4*)x1 + fbase;
                const float4* p2 = (const float4*)x2 + fbase;
                float4*       po = (float4*)out + fbase;
#pragma unroll
                for (int c = 0; c < 16; ++c) {
                    const float4 a = __ldcs(p1 + (size_t)c * (HWHW / 4));
                    const float4 v = __ldcs(p2 + (size_t)c * (HWHW / 4));
                    float4 o;
                    o.x = a.x * F1.x + v.x * F2.x;
                    o.y = a.y * F1.y + v.y * F2.y;
                    o.z = a.z * F1.z + v.z * F2.z;
                    o.w = a.w * F1.w + v.w * F2.w;
                    __stcs(po + (size_t)c * (HWHW / 4), o);
                }
            }
            asm volatile("bar.sync 2, 256;" ::: "memory");
            if (t == 0) cons_prog = j + 1;
        }
    }
}

extern "C" void kernel_launch(void* const* d_in, const int* in_sizes, int n_in,
                              void* d_out, int out_size) {
    const float* x1   = (const float*)d_in[0];
    const float* x2   = (const float*)d_in[1];
    const float* w    = (const float*)d_in[2];
    const float* bias = (const float*)d_in[3];
    float*       out  = (float*)d_out;

    k_reset<<<NUNITS / 256, 256>>>();
    k_fused<<<GRID, THREADS>>>(x1, x2, w, bias, out);
}